// round 7
// baseline (speedup 1.0000x reference)
#include <cuda_runtime.h>
#include <cstddef>

// Problem constants (fixed shapes)
#define NB 8    // batch
#define CC 8    // channels
#define TT 600  // time frames
#define FF 513  // freq bins
#define TS 20   // T-split chunks
#define TCH (TT / TS)       // 30 frames per chunk
#define NP 16               // partial entries: 8 re(nume) + 8 im(nume)
#define FBLK 5              // ceil(513/128) f-blocks of 128 threads

// Task layout (dependency-sorted):
#define SPN (FBLK * TS)           // snum tasks per n = 100
#define S_TOT (NB * SPN)          // 800
#define WPN 129                   // weight tasks per n (4 f's per task)
#define W_TOT (NB * WPN)          // 1032
#define BTB 8                     // t's per bf task
#define BPN (FBLK * (TT / BTB))   // bf tasks per n = 5*75 = 375
#define B_TOT (NB * BPN)          // 3000
#define T_TOT (S_TOT + W_TOT + B_TOT)  // 4832

__device__ float g_part[(size_t)TS * NB * NP * FF];  // ~5.3 MB partials
__device__ float g_w[(size_t)NB * CC * 2 * FF];      // conj(w), [n][c][re/im][f]
__device__ int g_task;
__device__ int g_snum_done[NB];
__device__ int g_w_done[NB];

__global__ void init_kernel() {
    if (threadIdx.x < NB) {
        g_snum_done[threadIdx.x] = 0;
        g_w_done[threadIdx.x] = 0;
    }
    if (threadIdx.x == 0) g_task = 0;
}

// ---------------------------------------------------------------------------
// Phase 1: partial nume_c = sum_t x_c * s_t, with s_t = sum_e conj(x_e) d_e.
// (phi never materialized; deno recovered later as conj(d)·nume.)
// ---------------------------------------------------------------------------
__device__ void snum_task(const float* __restrict__ x,
                          const float* __restrict__ sv,
                          int n, int z, int fb, int tid) {
    int f = fb * 128 + tid;
    if (f < FF) {
        float dr[CC], di[CC];
#pragma unroll
        for (int c = 0; c < CC; ++c) {
            dr[c] = sv[(size_t)(0 * FF + f) * CC + c];
            di[c] = sv[(size_t)(1 * FF + f) * CC + c];
        }

        float numr[CC], numi[CC];
#pragma unroll
        for (int c = 0; c < CC; ++c) { numr[c] = 0.f; numi[c] = 0.f; }

        const size_t chanStride = (size_t)TT * FF;
        const float* xr = x + (size_t)(n * 2 + 0) * CC * chanStride + f;
        const float* xi = x + (size_t)(n * 2 + 1) * CC * chanStride + f;

        int t0 = z * TCH;
        float a[2][CC], b[2][CC];
#pragma unroll
        for (int s = 0; s < 2; ++s) {
            size_t toff = (size_t)(t0 + s) * FF;
#pragma unroll
            for (int c = 0; c < CC; ++c) {
                a[s][c] = xr[(size_t)c * chanStride + toff];
                b[s][c] = xi[(size_t)c * chanStride + toff];
            }
        }

#pragma unroll 2
        for (int i = 0; i < TCH; ++i) {
            const int s = i & 1;
            float na[CC], nb[CC];
            if (i < TCH - 2) {
                size_t toff2 = (size_t)(t0 + i + 2) * FF;
#pragma unroll
                for (int c = 0; c < CC; ++c) {
                    na[c] = xr[(size_t)c * chanStride + toff2];
                    nb[c] = xi[(size_t)c * chanStride + toff2];
                }
            }
            float sr = 0.f, si = 0.f;
#pragma unroll
            for (int c = 0; c < CC; ++c) {
                sr += a[s][c] * dr[c] + b[s][c] * di[c];
                si += a[s][c] * di[c] - b[s][c] * dr[c];
            }
#pragma unroll
            for (int c = 0; c < CC; ++c) {
                numr[c] += a[s][c] * sr - b[s][c] * si;
                numi[c] += a[s][c] * si + b[s][c] * sr;
            }
            if (i < TCH - 2) {
#pragma unroll
                for (int c = 0; c < CC; ++c) { a[s][c] = na[c]; b[s][c] = nb[c]; }
            }
        }

        float* pb = g_part + ((size_t)(z * NB + n) * NP) * FF + f;
#pragma unroll
        for (int c = 0; c < CC; ++c) {
            pb[(size_t)c * FF] = numr[c];
            pb[(size_t)(8 + c) * FF] = numi[c];
        }
    }
    __threadfence();
    __syncthreads();
    if (tid == 0) atomicAdd(&g_snum_done[n], 1);
}

// ---------------------------------------------------------------------------
// Phase 2: warp per (n,f): reduce TS partials via shuffle, solve conj(w).
// ---------------------------------------------------------------------------
__device__ void weight_task(const float* __restrict__ sv, int n, int tf, int tid) {
    int wid = tid >> 5;
    int lane = tid & 31;
    int f = tf * 4 + wid;
    bool valid = (f < FF);
    int fc = valid ? f : 0;

    float v[NP];
    if (lane < TS) {
        const float* pb = g_part + ((size_t)(lane * NB + n) * NP) * FF + fc;
#pragma unroll
        for (int k = 0; k < NP; ++k) v[k] = pb[(size_t)k * FF];
    } else {
#pragma unroll
        for (int k = 0; k < NP; ++k) v[k] = 0.f;
    }

#pragma unroll
    for (int off = 16; off >= 1; off >>= 1) {
#pragma unroll
        for (int k = 0; k < NP; ++k)
            v[k] += __shfl_down_sync(0xffffffffu, v[k], off);
    }

    if (lane == 0 && valid) {
        const float invT = 1.0f / (float)TT;
        const float LOADC = 0.001f * 0.7071067811865475f;

        float dr[CC], di[CC];
#pragma unroll
        for (int c = 0; c < CC; ++c) {
            dr[c] = sv[(size_t)(0 * FF + f) * CC + c];
            di[c] = sv[(size_t)(1 * FF + f) * CC + c];
        }
        float nr[CC], ni[CC];
#pragma unroll
        for (int c = 0; c < CC; ++c) {
            nr[c] = v[c] * invT + LOADC * (dr[c] - di[c]);
            ni[c] = v[8 + c] * invT + LOADC * (dr[c] + di[c]);
        }
        // deno = sum_c conj(d_c) * nume_c  (loading already inside nume)
        float der = 0.f, dei = 0.f;
#pragma unroll
        for (int c = 0; c < CC; ++c) {
            der += dr[c] * nr[c] + di[c] * ni[c];
            dei += dr[c] * ni[c] - di[c] * nr[c];
        }
        float inv = 1.0f / (der * der + dei * dei);
#pragma unroll
        for (int c = 0; c < CC; ++c) {
            float wr = (nr[c] * der + ni[c] * dei) * inv;
            float wi = (ni[c] * der - nr[c] * dei) * inv;
            g_w[((size_t)(n * CC + c) * 2 + 0) * FF + f] = wr;   // re(conj w)
            g_w[((size_t)(n * CC + c) * 2 + 1) * FF + f] = -wi;  // im(conj w)
        }
    }
    __threadfence();
    __syncthreads();
    if (tid == 0) atomicAdd(&g_w_done[n], 1);
}

// ---------------------------------------------------------------------------
// Phase 3: beamform 8 t's x 128 f's with conj(w), depth-2 pipeline.
// ---------------------------------------------------------------------------
__device__ void bf_task(const float* __restrict__ y, float* __restrict__ out,
                        int n, int tb, int fb, int tid) {
    int f = fb * 128 + tid;
    if (f >= FF) return;
    int t0 = tb * BTB;

    float cwr[CC], cwi[CC];
#pragma unroll
    for (int c = 0; c < CC; ++c) {
        cwr[c] = g_w[((size_t)(n * CC + c) * 2 + 0) * FF + f];
        cwi[c] = g_w[((size_t)(n * CC + c) * 2 + 1) * FF + f];
    }

    const size_t chanStride = (size_t)TT * FF;
    const float* yr = y + (size_t)(n * 2 + 0) * CC * chanStride + f;
    const float* yi = y + (size_t)(n * 2 + 1) * CC * chanStride + f;
    float* outr = out + (size_t)(n * 2 + 0) * TT * FF + f;
    float* outi = out + (size_t)(n * 2 + 1) * TT * FF + f;

    float a[2][CC], b[2][CC];
#pragma unroll
    for (int s = 0; s < 2; ++s) {
        size_t toff = (size_t)(t0 + s) * FF;
#pragma unroll
        for (int c = 0; c < CC; ++c) {
            a[s][c] = yr[(size_t)c * chanStride + toff];
            b[s][c] = yi[(size_t)c * chanStride + toff];
        }
    }

#pragma unroll
    for (int i = 0; i < BTB; ++i) {
        const int s = i & 1;
        float na[CC], nb[CC];
        if (i < BTB - 2) {
            size_t toff2 = (size_t)(t0 + i + 2) * FF;
#pragma unroll
            for (int c = 0; c < CC; ++c) {
                na[c] = yr[(size_t)c * chanStride + toff2];
                nb[c] = yi[(size_t)c * chanStride + toff2];
            }
        }
        float ar = 0.f, ai = 0.f;
#pragma unroll
        for (int c = 0; c < CC; ++c) {
            ar += cwr[c] * a[s][c] - cwi[c] * b[s][c];
            ai += cwr[c] * b[s][c] + cwi[c] * a[s][c];
        }
        size_t toff = (size_t)(t0 + i) * FF;
        outr[toff] = ar;
        outi[toff] = ai;
        if (i < BTB - 2) {
#pragma unroll
            for (int c = 0; c < CC; ++c) { a[s][c] = na[c]; b[s][c] = nb[c]; }
        }
    }
}

__device__ __forceinline__ void spin_until(volatile int* cnt, int target) {
    while (*cnt < target) __nanosleep(200);
}

// ---------------------------------------------------------------------------
// Persistent fused kernel: atomic task queue in dependency-sorted order.
// Overlaps snum(late n) with bf(early n) -> two independent memory streams.
// ---------------------------------------------------------------------------
__global__ void __launch_bounds__(128) fused_kernel(const float* __restrict__ mixture,
                                                    const float* __restrict__ target,
                                                    const float* __restrict__ sv,
                                                    float* __restrict__ out) {
    __shared__ int s_task;
    int tid = threadIdx.x;

    for (;;) {
        if (tid == 0) s_task = atomicAdd(&g_task, 1);
        __syncthreads();
        int t = s_task;
        if (t >= T_TOT) return;

        if (t < S_TOT) {
            int n = t / SPN;
            int rem = t - n * SPN;
            int z = rem / FBLK;
            int fb = rem - z * FBLK;
            snum_task(target, sv, n, z, fb, tid);
        } else if (t < S_TOT + W_TOT) {
            int w = t - S_TOT;
            int n = w / WPN;
            int tf = w - n * WPN;
            if (tid == 0) spin_until(&g_snum_done[n], SPN);
            __syncthreads();
            __threadfence();
            weight_task(sv, n, tf, tid);
        } else {
            int b = t - S_TOT - W_TOT;
            int n = b / BPN;
            int rem = b - n * BPN;
            int tb = rem / FBLK;
            int fb = rem - tb * FBLK;
            if (tid == 0) spin_until(&g_w_done[n], WPN);
            __syncthreads();
            __threadfence();
            bf_task(mixture, out, n, tb, fb, tid);
            __syncthreads();  // keep block together before next task grab
        }
    }
}

extern "C" void kernel_launch(void* const* d_in, const int* in_sizes, int n_in,
                              void* d_out, int out_size) {
    const float* mixture = (const float*)d_in[0];
    // d_in[1] = noise (unused by the reference computation)
    const float* target = (const float*)d_in[2];
    const float* sv = (const float*)d_in[3];
    float* out = (float*)d_out;

    init_kernel<<<1, 32>>>();
    fused_kernel<<<740, 128>>>(mixture, target, sv, out);
}